// round 4
// baseline (speedup 1.0000x reference)
#include <cuda_runtime.h>
#include <math.h>
#include <stdint.h>

#define S_TOK 257
#define D_DIM 1024
#define HID 4096
#define NLAYER 12
#define NC 256
#define CSZ 128
#define AGE_V 258
#define OBS_N 2048
#define OUT_N 512
#define HEADS 16
#define DH 64

// ---------------- scratch (device globals; no allocation allowed) ----------
__device__ float g_x[S_TOK * D_DIM];
__device__ float g_q[S_TOK * D_DIM];
__device__ float g_k[S_TOK * D_DIM];
__device__ float g_v[S_TOK * D_DIM];
__device__ float g_ao[S_TOK * D_DIM];
__device__ float g_ffn[S_TOK * HID];
__device__ float g_part[4 * S_TOK * D_DIM];   // split-K partials (KS<=4)

// ---------------- helpers ---------------------------------------------------
__device__ __forceinline__ float warpMax(float v) {
#pragma unroll
    for (int o = 16; o; o >>= 1) v = fmaxf(v, __shfl_xor_sync(0xffffffffu, v, o));
    return v;
}
__device__ __forceinline__ float warpSum(float v) {
#pragma unroll
    for (int o = 16; o; o >>= 1) v += __shfl_xor_sync(0xffffffffu, v, o);
    return v;
}
__device__ __forceinline__ uint32_t f2tf(float f) {
    uint32_t u;
    asm("cvt.rna.tf32.f32 %0, %1;" : "=r"(u) : "f"(f));
    return u;
}
__device__ __forceinline__ void mma1688(float (&d)[4], const uint32_t (&a)[4], const uint32_t (&b)[2]) {
    asm volatile(
        "mma.sync.aligned.m16n8k8.row.col.f32.tf32.tf32.f32 "
        "{%0,%1,%2,%3}, {%4,%5,%6,%7}, {%8,%9}, {%0,%1,%2,%3};\n"
        : "+f"(d[0]), "+f"(d[1]), "+f"(d[2]), "+f"(d[3])
        : "r"(a[0]), "r"(a[1]), "r"(a[2]), "r"(a[3]), "r"(b[0]), "r"(b[1]));
}

// ============================================================================
// tf32 GEMM core: C[M,N] = A[M,K] @ B[N,K]^T.
// Block 128x64, BK=32, 256 threads (8 warps, 4x2 grid, warp tile 32x32).
// Double-buffered smem (dynamic, 55.3KB) + register-staged global prefetch:
// ONE __syncthreads per k-tile. Smem stride 36 -> conflict-free frag loads.
// ============================================================================
#define AS_STRIDE 36
#define ABUF (128 * AS_STRIDE)
#define BBUF (64 * AS_STRIDE)
#define GEMM_SMEM_BYTES ((2 * ABUF + 2 * BBUF) * 4)

__device__ __forceinline__ void tf32_core_128(
    const float* __restrict__ A, const float* __restrict__ B,
    int M, int K, int bm, int bn, int kbeg, int ktiles,
    float (&acc)[2][4][4], uint32_t* __restrict__ As, uint32_t* __restrict__ Bs)
{
    const int tid = threadIdx.x;
    const int lane = tid & 31, wid = tid >> 5;
    const int wm = wid & 3, wn = wid >> 2;
    const int fr = lane >> 2, fc = lane & 3;

    int arow[4], akq[4];
    bool aval[4];
    const float* aptr[4];
#pragma unroll
    for (int i = 0; i < 4; i++) {
        const int idx = tid + i * 256;
        const int row = idx >> 3, kq = (idx & 7) << 2;
        arow[i] = row; akq[i] = kq;
        aval[i] = (bm + row) < M;
        aptr[i] = A + (size_t)(bm + row) * K + kbeg + kq;
    }
    int brow[2], bkq[2];
    const float* bptr[2];
#pragma unroll
    for (int i = 0; i < 2; i++) {
        const int idx = tid + i * 256;
        const int row = idx >> 3, kq = (idx & 7) << 2;
        brow[i] = row; bkq[i] = kq;
        bptr[i] = B + (size_t)(bn + row) * K + kbeg + kq;
    }

    float4 pa[4], pb[2];
#pragma unroll
    for (int i = 0; i < 4; i++)
        pa[i] = aval[i] ? *(const float4*)(aptr[i]) : make_float4(0.f, 0.f, 0.f, 0.f);
#pragma unroll
    for (int i = 0; i < 2; i++)
        pb[i] = *(const float4*)(bptr[i]);

#pragma unroll
    for (int i = 0; i < 4; i++) {
        uint32_t* p = As + arow[i] * AS_STRIDE + akq[i];
        p[0] = f2tf(pa[i].x); p[1] = f2tf(pa[i].y); p[2] = f2tf(pa[i].z); p[3] = f2tf(pa[i].w);
    }
#pragma unroll
    for (int i = 0; i < 2; i++) {
        uint32_t* p = Bs + brow[i] * AS_STRIDE + bkq[i];
        p[0] = f2tf(pb[i].x); p[1] = f2tf(pb[i].y); p[2] = f2tf(pb[i].z); p[3] = f2tf(pb[i].w);
    }
    __syncthreads();

    int buf = 0;
    for (int kt = 0; kt < ktiles; kt++) {
        const bool has_next = (kt + 1 < ktiles);
        if (has_next) {
            const int off = (kt + 1) * 32;
#pragma unroll
            for (int i = 0; i < 4; i++)
                pa[i] = aval[i] ? *(const float4*)(aptr[i] + off) : make_float4(0.f, 0.f, 0.f, 0.f);
#pragma unroll
            for (int i = 0; i < 2; i++)
                pb[i] = *(const float4*)(bptr[i] + off);
        }
        const uint32_t* Ab = As + buf * ABUF;
        const uint32_t* Bb = Bs + buf * BBUF;
#pragma unroll
        for (int k0 = 0; k0 < 32; k0 += 8) {
            uint32_t af[2][4], bf[4][2];
#pragma unroll
            for (int mi = 0; mi < 2; mi++) {
                const int r = wm * 32 + mi * 16 + fr;
                af[mi][0] = Ab[r * AS_STRIDE + k0 + fc];
                af[mi][1] = Ab[(r + 8) * AS_STRIDE + k0 + fc];
                af[mi][2] = Ab[r * AS_STRIDE + k0 + fc + 4];
                af[mi][3] = Ab[(r + 8) * AS_STRIDE + k0 + fc + 4];
            }
#pragma unroll
            for (int ni = 0; ni < 4; ni++) {
                const int c = wn * 32 + ni * 8 + fr;
                bf[ni][0] = Bb[c * AS_STRIDE + k0 + fc];
                bf[ni][1] = Bb[c * AS_STRIDE + k0 + fc + 4];
            }
#pragma unroll
            for (int mi = 0; mi < 2; mi++)
#pragma unroll
                for (int ni = 0; ni < 4; ni++)
                    mma1688(acc[mi][ni], af[mi], bf[ni]);
        }
        if (has_next) {
            const int nb = buf ^ 1;
            uint32_t* An = As + nb * ABUF;
            uint32_t* Bn = Bs + nb * BBUF;
#pragma unroll
            for (int i = 0; i < 4; i++) {
                uint32_t* p = An + arow[i] * AS_STRIDE + akq[i];
                p[0] = f2tf(pa[i].x); p[1] = f2tf(pa[i].y); p[2] = f2tf(pa[i].z); p[3] = f2tf(pa[i].w);
            }
#pragma unroll
            for (int i = 0; i < 2; i++) {
                uint32_t* p = Bn + brow[i] * AS_STRIDE + bkq[i];
                p[0] = f2tf(pb[i].x); p[1] = f2tf(pb[i].y); p[2] = f2tf(pb[i].z); p[3] = f2tf(pb[i].w);
            }
            __syncthreads();
            buf = nb;
        }
    }
}

// ---- fused QKV ---------------------------------------------------------------
__global__ __launch_bounds__(256) void gemm_qkv_kernel(
    const float* __restrict__ A,
    const float* __restrict__ Wq_, const float* __restrict__ Wk_, const float* __restrict__ Wv_,
    const float* __restrict__ bq_, const float* __restrict__ bk_, const float* __restrict__ bv_,
    float* __restrict__ Q, float* __restrict__ Ko, float* __restrict__ V,
    int M, int N, int K)
{
    extern __shared__ uint32_t smem_u[];
    uint32_t* As = smem_u;
    uint32_t* Bs = smem_u + 2 * ABUF;
    const int z = blockIdx.z;
    const float* B    = (z == 0) ? Wq_ : (z == 1) ? Wk_ : Wv_;
    const float* bias = (z == 0) ? bq_ : (z == 1) ? bk_ : bv_;
    float* C          = (z == 0) ? Q   : (z == 1) ? Ko  : V;

    const int bm = blockIdx.y * 128;
    const int bn = blockIdx.x * 64;
    float acc[2][4][4] = {};
    tf32_core_128(A, B, M, K, bm, bn, 0, K / 32, acc, As, Bs);

    const int lane = threadIdx.x & 31, wid = threadIdx.x >> 5;
    const int wm = wid & 3, wn = wid >> 2;
    const int fr = lane >> 2, fc = lane & 3;
#pragma unroll
    for (int mi = 0; mi < 2; mi++)
#pragma unroll
        for (int ni = 0; ni < 4; ni++) {
            const int r = bm + wm * 32 + mi * 16 + fr;
            const int c = bn + wn * 32 + ni * 8 + fc * 2;
            const float bx = bias[c], by = bias[c + 1];
            if (r < M) {
                float2 o = {acc[mi][ni][0] + bx, acc[mi][ni][1] + by};
                *(float2*)(C + (size_t)r * N + c) = o;
            }
            if (r + 8 < M) {
                float2 o = {acc[mi][ni][2] + bx, acc[mi][ni][3] + by};
                *(float2*)(C + (size_t)(r + 8) * N + c) = o;
            }
        }
}

// ---- direct GEMM with bias (+relu) -------------------------------------------
__global__ __launch_bounds__(256) void gemm_direct_kernel(
    const float* __restrict__ A, const float* __restrict__ B,
    const float* __restrict__ bias, float* __restrict__ C,
    int M, int N, int K, int relu_flag)
{
    extern __shared__ uint32_t smem_u[];
    uint32_t* As = smem_u;
    uint32_t* Bs = smem_u + 2 * ABUF;
    const int bm = blockIdx.y * 128;
    const int bn = blockIdx.x * 64;
    float acc[2][4][4] = {};
    tf32_core_128(A, B, M, K, bm, bn, 0, K / 32, acc, As, Bs);

    const int lane = threadIdx.x & 31, wid = threadIdx.x >> 5;
    const int wm = wid & 3, wn = wid >> 2;
    const int fr = lane >> 2, fc = lane & 3;
#pragma unroll
    for (int mi = 0; mi < 2; mi++)
#pragma unroll
        for (int ni = 0; ni < 4; ni++) {
            const int r = bm + wm * 32 + mi * 16 + fr;
            const int c = bn + wn * 32 + ni * 8 + fc * 2;
            const float bx = bias[c], by = bias[c + 1];
            if (r < M) {
                float2 o = {acc[mi][ni][0] + bx, acc[mi][ni][1] + by};
                if (relu_flag) { o.x = fmaxf(o.x, 0.f); o.y = fmaxf(o.y, 0.f); }
                *(float2*)(C + (size_t)r * N + c) = o;
            }
            if (r + 8 < M) {
                float2 o = {acc[mi][ni][2] + bx, acc[mi][ni][3] + by};
                if (relu_flag) { o.x = fmaxf(o.x, 0.f); o.y = fmaxf(o.y, 0.f); }
                *(float2*)(C + (size_t)(r + 8) * N + c) = o;
            }
        }
}

// ---- split-K GEMM (raw partials) ---------------------------------------------
__global__ __launch_bounds__(256) void gemm_splitk_kernel(
    const float* __restrict__ A, const float* __restrict__ B,
    float* __restrict__ part, int M, int N, int K, int klen)
{
    extern __shared__ uint32_t smem_u[];
    uint32_t* As = smem_u;
    uint32_t* Bs = smem_u + 2 * ABUF;
    const int bm = blockIdx.y * 128;
    const int bn = blockIdx.x * 64;
    const int z = blockIdx.z;
    float acc[2][4][4] = {};
    tf32_core_128(A, B, M, K, bm, bn, z * klen, klen / 32, acc, As, Bs);

    float* C = part + (size_t)z * M * N;
    const int lane = threadIdx.x & 31, wid = threadIdx.x >> 5;
    const int wm = wid & 3, wn = wid >> 2;
    const int fr = lane >> 2, fc = lane & 3;
#pragma unroll
    for (int mi = 0; mi < 2; mi++)
#pragma unroll
        for (int ni = 0; ni < 4; ni++) {
            const int r = bm + wm * 32 + mi * 16 + fr;
            const int c = bn + wn * 32 + ni * 8 + fc * 2;
            if (r < M) {
                float2 o = {acc[mi][ni][0], acc[mi][ni][1]};
                *(float2*)(C + (size_t)r * N + c) = o;
            }
            if (r + 8 < M) {
                float2 o = {acc[mi][ni][2], acc[mi][ni][3]};
                *(float2*)(C + (size_t)(r + 8) * N + c) = o;
            }
        }
}

// ---- fused combine(split-K) + bias + residual + LayerNorm --------------------
__global__ __launch_bounds__(256) void combine_ln_kernel(
    const float* __restrict__ part, int KS,
    const float* __restrict__ bias, const float* __restrict__ res,
    const float* __restrict__ g, const float* __restrict__ b,
    float* __restrict__ out, int M)
{
    const int row = blockIdx.x;
    const int tid = threadIdx.x;
    const int lane = tid & 31, warp = tid >> 5;
    __shared__ float rs[8], rs2[8];
    __shared__ float smv[2];

    float4 s = ((const float4*)(part + (size_t)row * D_DIM))[tid];
    for (int z = 1; z < KS; z++) {
        const float4 t = ((const float4*)(part + ((size_t)z * M + row) * D_DIM))[tid];
        s.x += t.x; s.y += t.y; s.z += t.z; s.w += t.w;
    }
    const float4 b4 = ((const float4*)bias)[tid];
    s.x += b4.x; s.y += b4.y; s.z += b4.z; s.w += b4.w;
    const float4 r4 = ((const float4*)(res + (size_t)row * D_DIM))[tid];
    s.x += r4.x; s.y += r4.y; s.z += r4.z; s.w += r4.w;

    float sum = s.x + s.y + s.z + s.w;
    float sq = s.x * s.x + s.y * s.y + s.z * s.z + s.w * s.w;
    sum = warpSum(sum); sq = warpSum(sq);
    if (lane == 0) { rs[warp] = sum; rs2[warp] = sq; }
    __syncthreads();
    if (warp == 0) {
        float t = (lane < 8) ? rs[lane] : 0.f;
        float t2 = (lane < 8) ? rs2[lane] : 0.f;
        t = warpSum(t); t2 = warpSum(t2);
        if (lane == 0) {
            const float mean = t * (1.0f / D_DIM);
            const float var = t2 * (1.0f / D_DIM) - mean * mean;
            smv[0] = mean;
            smv[1] = rsqrtf(var + 1e-5f);
        }
    }
    __syncthreads();
    const float mean = smv[0], inv = smv[1];
    const float4 g4 = ((const float4*)g)[tid];
    const float4 be4 = ((const float4*)b)[tid];
    float4 o;
    o.x = (s.x - mean) * inv * g4.x + be4.x;
    o.y = (s.y - mean) * inv * g4.y + be4.y;
    o.z = (s.z - mean) * inv * g4.z + be4.z;
    o.w = (s.w - mean) * inv * g4.w + be4.w;
    ((float4*)(out + (size_t)row * D_DIM))[tid] = o;
}

// ---------------- attention: block per (head, 16-query tile) ----------------
#define QT 16
__global__ __launch_bounds__(256) void attn3_kernel(
    const float* __restrict__ q, const float* __restrict__ k,
    const float* __restrict__ v, float* __restrict__ o)
{
    const int h = blockIdx.x;
    const int qt = blockIdx.y * QT;
    const int tid = threadIdx.x, lane = tid & 31, warp = tid >> 5;

    __shared__ float Qs[QT][68];
    __shared__ float T[64][68];
    __shared__ float sc[QT][261];
    __shared__ float inv_s[QT];

    const int nq = min(QT, S_TOK - qt);

    // load Q tile (256 threads = 16 rows x 16 float4)
    {
        const int r = tid >> 4, c4 = (tid & 15) << 2;
        float4 val = (r < nq) ? *(const float4*)(q + (size_t)(qt + r) * D_DIM + h * DH + c4)
                              : make_float4(0.f, 0.f, 0.f, 0.f);
        *(float4*)&Qs[r][c4] = val;
    }

    const int qrow = tid & 15, jg = tid >> 4;

    // phase 1: scores
    for (int j0 = 0; j0 < S_TOK; j0 += 64) {
        const int jn = min(64, S_TOK - j0);
        __syncthreads();
#pragma unroll
        for (int i = 0; i < 4; i++) {
            const int idx = tid + i * 256;
            const int r = idx >> 4, c4 = (idx & 15) << 2;
            float4 val = (r < jn) ? *(const float4*)(k + (size_t)(j0 + r) * D_DIM + h * DH + c4)
                                  : make_float4(0.f, 0.f, 0.f, 0.f);
            *(float4*)&T[r][c4] = val;
        }
        __syncthreads();
        for (int jj = jg; jj < jn; jj += 16) {
            const float4* qr4 = (const float4*)Qs[qrow];
            const float4* kr4 = (const float4*)T[jj];
            float s = 0.f;
#pragma unroll
            for (int t = 0; t < 16; t++) {
                const float4 a = qr4[t], bb = kr4[t];
                s += a.x * bb.x + a.y * bb.y + a.z * bb.z + a.w * bb.w;
            }
            sc[qrow][j0 + jj] = s * 0.125f;
        }
    }
    __syncthreads();

    // phase 2: softmax (one warp -> 2 rows)
#pragma unroll
    for (int ri = 0; ri < 2; ri++) {
        const int r = warp * 2 + ri;
        if (r < nq) {
            float m = -1e30f;
            for (int j = lane; j < S_TOK; j += 32) m = fmaxf(m, sc[r][j]);
            m = warpMax(m);
            float ssum = 0.f;
            for (int j = lane; j < S_TOK; j += 32) {
                const float e = __expf(sc[r][j] - m);
                sc[r][j] = e;
                ssum += e;
            }
            ssum = warpSum(ssum);
            if (lane == 0) inv_s[r] = 1.0f / ssum;
        }
    }
    __syncthreads();

    // phase 3: attn @ V  (thread = (qrow, 4-dim group))
    const int db = (tid >> 4) << 2;
    float4 acc = make_float4(0.f, 0.f, 0.f, 0.f);
    for (int j0 = 0; j0 < S_TOK; j0 += 64) {
        const int jn = min(64, S_TOK - j0);
        __syncthreads();
#pragma unroll
        for (int i = 0; i < 4; i++) {
            const int idx = tid + i * 256;
            const int r = idx >> 4, c4 = (idx & 15) << 2;
            float4 val = (r < jn) ? *(const float4*)(v + (size_t)(j0 + r) * D_DIM + h * DH + c4)
                                  : make_float4(0.f, 0.f, 0.f, 0.f);
            *(float4*)&T[r][c4] = val;
        }
        __syncthreads();
        for (int jj = 0; jj < jn; jj++) {
            const float w = sc[qrow][j0 + jj];
            const float4 vv = *(const float4*)&T[jj][db];
            acc.x += w * vv.x; acc.y += w * vv.y; acc.z += w * vv.z; acc.w += w * vv.w;
        }
    }
    if (qrow < nq) {
        const float iv = inv_s[qrow];
        float4 oo = {acc.x * iv, acc.y * iv, acc.z * iv, acc.w * iv};
        *(float4*)(o + (size_t)(qt + qrow) * D_DIM + h * DH + db) = oo;
    }
}

// ---------------- matvec (embeddings / heads) -------------------------------
__global__ __launch_bounds__(256) void matvec_kernel(
    const float* __restrict__ W, const float* __restrict__ bias,
    const float* __restrict__ x, float* __restrict__ out,
    int N, int K, int act)
{
    __shared__ float xs[OBS_N];
    const int tid = threadIdx.x;
    for (int i = tid; i < K; i += 256) xs[i] = x[i];
    __syncthreads();
    const int warp = tid >> 5, lane = tid & 31;
    const int n = blockIdx.x * 8 + warp;
    if (n >= N) return;
    const float4* wr = reinterpret_cast<const float4*>(W + (size_t)n * K);
    const float4* x4 = reinterpret_cast<const float4*>(xs);
    float s = 0.f;
    const int K4 = K >> 2;
    for (int kb = lane; kb < K4; kb += 32) {
        const float4 w = wr[kb], xv = x4[kb];
        s += w.x * xv.x + w.y * xv.y + w.z * xv.z + w.w * xv.w;
    }
    s = warpSum(s);
    if (lane == 0) {
        s += bias[n];
        if (act == 1) s = fmaxf(s, 0.f);
        else if (act == 2) s = tanhf(s);
        out[n] = s;
    }
}

// ---------------- concept embedding (rows 1..256 of x) ---------------------
__global__ __launch_bounds__(256) void cemb_kernel(
    const float* __restrict__ concepts, const float* __restrict__ Wc,
    const float* __restrict__ bc, const float* __restrict__ Wage,
    const float* __restrict__ bage, float* __restrict__ x)
{
    const int i = blockIdx.x;
    const int tid = threadIdx.x;
    __shared__ float cv[CSZ];
    if (tid < CSZ) cv[tid] = concepts[i * CSZ + tid];
    __syncthreads();
    const float agef = (float)i / 256.0f;
    for (int d = tid; d < D_DIM; d += 256) {
        const float4* wr = reinterpret_cast<const float4*>(Wc + (size_t)d * CSZ);
        const float4* c4 = reinterpret_cast<const float4*>(cv);
        float s = 0.f;
#pragma unroll
        for (int t = 0; t < CSZ / 4; t++) {
            const float4 w = wr[t], c = c4[t];
            s += w.x * c.x + w.y * c.y + w.z * c.z + w.w * c.w;
        }
        s += bc[d] + Wage[(size_t)d * AGE_V + i] + agef * Wage[(size_t)d * AGE_V + (AGE_V - 1)] + bage[d];
        x[(size_t)(i + 1) * D_DIM + d] = s;
    }
}

// ---------------- host launch ----------------------------------------------
extern "C" void kernel_launch(void* const* d_in, const int* in_sizes, int n_in,
                              void* d_out, int out_size)
{
    const float* observation = (const float*)d_in[0];
    const float* concepts    = (const float*)d_in[1];
    const float* W_core = (const float*)d_in[2];
    const float* b_core = (const float*)d_in[3];
    const float* W_cemb = (const float*)d_in[4];
    const float* b_cemb = (const float*)d_in[5];
    const float* W_age  = (const float*)d_in[6];
    const float* b_age  = (const float*)d_in[7];
    const float* Wq = (const float*)d_in[8];
    const float* bq = (const float*)d_in[9];
    const float* Wk = (const float*)d_in[10];
    const float* bk = (const float*)d_in[11];
    const float* Wv = (const float*)d_in[12];
    const float* bv = (const float*)d_in[13];
    const float* Wo = (const float*)d_in[14];
    const float* bo = (const float*)d_in[15];
    const float* ln1_g = (const float*)d_in[16];
    const float* ln1_b = (const float*)d_in[17];
    const float* W1 = (const float*)d_in[18];
    const float* b1 = (const float*)d_in[19];
    const float* W2 = (const float*)d_in[20];
    const float* b2 = (const float*)d_in[21];
    const float* ln2_g = (const float*)d_in[22];
    const float* ln2_b = (const float*)d_in[23];
    const float* W_concept = (const float*)d_in[24];
    const float* b_concept = (const float*)d_in[25];
    const float* W_out = (const float*)d_in[26];
    const float* b_out = (const float*)d_in[27];

    float *x, *q, *k, *v, *ao, *ffn, *part;
    cudaGetSymbolAddress((void**)&x, g_x);
    cudaGetSymbolAddress((void**)&q, g_q);
    cudaGetSymbolAddress((void**)&k, g_k);
    cudaGetSymbolAddress((void**)&v, g_v);
    cudaGetSymbolAddress((void**)&ao, g_ao);
    cudaGetSymbolAddress((void**)&ffn, g_ffn);
    cudaGetSymbolAddress((void**)&part, g_part);

    // raise dynamic smem limit for GEMM kernels (idempotent host calls)
    cudaFuncSetAttribute(gemm_qkv_kernel,    cudaFuncAttributeMaxDynamicSharedMemorySize, GEMM_SMEM_BYTES);
    cudaFuncSetAttribute(gemm_direct_kernel, cudaFuncAttributeMaxDynamicSharedMemorySize, GEMM_SMEM_BYTES);
    cudaFuncSetAttribute(gemm_splitk_kernel, cudaFuncAttributeMaxDynamicSharedMemorySize, GEMM_SMEM_BYTES);

    const int M = S_TOK;
    const dim3 blk(256);
    const int MT = (M + 127) / 128;               // 3 m-tiles
    const dim3 grid_qkv(D_DIM / 64, MT, 3);       // 144 blocks
    const dim3 grid_o(D_DIM / 64, MT, 4);         // split-K=4, 192 blocks
    const dim3 grid_w1(HID / 64, MT, 1);          // 192 blocks
    const dim3 grid_w2(D_DIM / 64, MT, 4);        // split-K=4, 192 blocks
    const dim3 grid_attn(HEADS, (S_TOK + QT - 1) / QT);   // 16 x 17

    // --- embeddings ---
    matvec_kernel<<<D_DIM / 8, 256>>>(W_core, b_core, observation, x, D_DIM, OBS_N, 0);
    cemb_kernel<<<NC, 256>>>(concepts, W_cemb, b_cemb, W_age, b_age, x);

    // --- transformer layers ---
    for (int l = 0; l < NLAYER; l++) {
        const size_t od  = (size_t)l * D_DIM * D_DIM;
        const size_t ob  = (size_t)l * D_DIM;
        const size_t o1w = (size_t)l * HID * D_DIM;
        const size_t o1b = (size_t)l * HID;

        gemm_qkv_kernel<<<grid_qkv, blk, GEMM_SMEM_BYTES>>>(
            x, Wq + od, Wk + od, Wv + od, bq + ob, bk + ob, bv + ob,
            q, k, v, M, D_DIM, D_DIM);

        attn3_kernel<<<grid_attn, blk>>>(q, k, v, ao);

        gemm_splitk_kernel<<<grid_o, blk, GEMM_SMEM_BYTES>>>(
            ao, Wo + od, part, M, D_DIM, D_DIM, D_DIM / 4);
        combine_ln_kernel<<<M, 256>>>(part, 4, bo + ob, x, ln1_g + ob, ln1_b + ob, x, M);

        gemm_direct_kernel<<<grid_w1, blk, GEMM_SMEM_BYTES>>>(
            x, W1 + o1w, b1 + o1b, ffn, M, HID, D_DIM, 1);
        gemm_splitk_kernel<<<grid_w2, blk, GEMM_SMEM_BYTES>>>(
            ffn, W2 + o1w, part, M, D_DIM, HID, HID / 4);
        combine_ln_kernel<<<M, 256>>>(part, 4, b2 + ob, x, ln2_g + ob, ln2_b + ob, x, M);
    }

    // --- heads (node 0) -> d_out = [output(512) | new_concept(128)] ---
    float* out = (float*)d_out;
    matvec_kernel<<<OUT_N / 8, 256>>>(W_out, b_out, x, out, OUT_N, D_DIM, 1);
    matvec_kernel<<<CSZ / 8, 256>>>(W_concept, b_concept, x, out + OUT_N, CSZ, D_DIM, 2);

    (void)in_sizes; (void)n_in; (void)out_size;
}